// round 1
// baseline (speedup 1.0000x reference)
#include <cuda_runtime.h>

#define NN 100000
#define NE 1200000
#define D  64

// Scratch (device globals — no allocation allowed)
__device__ float g_dis[NN];        // degree, then rsqrt(degree)
__device__ float g_h[NN * D];      // h = x @ W^T

// ---------------------------------------------------------------------------
// 1) deg init (self-loop contributes weight 1.0)
__global__ void k_init_deg() {
    int i = blockIdx.x * blockDim.x + threadIdx.x;
    if (i < NN) g_dis[i] = 1.0f;
}

// 2) deg scatter: deg[dst] += ew
__global__ void k_deg(const int* __restrict__ dst, const float* __restrict__ ew) {
    int e = blockIdx.x * blockDim.x + threadIdx.x;
    if (e < NE) atomicAdd(&g_dis[dst[e]], ew[e]);
}

// 3) dis = rsqrt(deg)   (deg >= 1 always, matches where(deg>0, rsqrt, 0))
__global__ void k_rsqrt() {
    int i = blockIdx.x * blockDim.x + threadIdx.x;
    if (i < NN) g_dis[i] = rsqrtf(g_dis[i]);
}

// ---------------------------------------------------------------------------
// 4) GEMM h = x @ W^T, fused with self-loop contribution:
//    g_h[i] = h_i ;  out[i] = dis[i]^2 * h_i   (initializes every out element)
// Block: 256 threads (8 warps), each warp computes ROWS_PER_WARP rows.
// W transposed in smem: Wt[k*64 + j] = W[j*64 + k]; lane owns cols {2l, 2l+1}.
#define ROWS_PER_WARP 16
__global__ __launch_bounds__(256) void k_gemm(const float* __restrict__ x,
                                              const float* __restrict__ W,
                                              float* __restrict__ out) {
    __shared__ float Wt[D * D];
    for (int t = threadIdx.x; t < D * D; t += 256) {
        int j = t / D, k = t % D;          // W read coalesced, write transposed
        Wt[k * D + j] = W[t];
    }
    __syncthreads();

    const int warp = threadIdx.x >> 5;
    const int lane = threadIdx.x & 31;
    int base = blockIdx.x * (8 * ROWS_PER_WARP) + warp * ROWS_PER_WARP;

    for (int r = 0; r < ROWS_PER_WARP; r++) {
        int i = base + r;
        if (i >= NN) return;               // warp-uniform
        float xa = x[i * D + lane];
        float xb = x[i * D + 32 + lane];
        float2 acc = make_float2(0.f, 0.f);
        #pragma unroll
        for (int k = 0; k < 32; k++) {
            float xv = __shfl_sync(0xffffffffu, xa, k);
            float2 w = *(const float2*)&Wt[k * D + 2 * lane];
            acc.x = fmaf(xv, w.x, acc.x);
            acc.y = fmaf(xv, w.y, acc.y);
        }
        #pragma unroll
        for (int k = 0; k < 32; k++) {
            float xv = __shfl_sync(0xffffffffu, xb, k);
            float2 w = *(const float2*)&Wt[(k + 32) * D + 2 * lane];
            acc.x = fmaf(xv, w.x, acc.x);
            acc.y = fmaf(xv, w.y, acc.y);
        }
        *(float2*)&g_h[i * D + 2 * lane] = acc;
        float s = g_dis[i];
        float ss = s * s;
        float2 o = make_float2(ss * acc.x, ss * acc.y);
        *(float2*)&out[i * D + 2 * lane] = o;
    }
}

// ---------------------------------------------------------------------------
// 5) Edge scatter: out[dst] += dis[src]*ew*dis[dst] * h[src]
// One thread handles a float4 chunk (16 threads per edge).
// red.global.add.v4.f32 (sm_90+) -> 16 reduction instrs / edge instead of 64.
__global__ __launch_bounds__(256) void k_msg(const int* __restrict__ src,
                                             const int* __restrict__ dst,
                                             const float* __restrict__ ew,
                                             float* __restrict__ out) {
    long long t = (long long)blockIdx.x * blockDim.x + threadIdx.x;
    int e = (int)(t >> 4);
    if (e >= NE) return;
    int c = (int)(t & 15) << 2;

    int r  = src[e];
    int cl = dst[e];
    float norm = g_dis[r] * ew[e] * g_dis[cl];

    float4 hv = *(const float4*)&g_h[r * D + c];
    float4 m;
    m.x = norm * hv.x;
    m.y = norm * hv.y;
    m.z = norm * hv.z;
    m.w = norm * hv.w;

    float* p = &out[cl * D + c];
    asm volatile("red.global.add.v4.f32 [%0], {%1, %2, %3, %4};"
                 :: "l"(p), "f"(m.x), "f"(m.y), "f"(m.z), "f"(m.w)
                 : "memory");
}

// ---------------------------------------------------------------------------
// 6) out = relu(out + b)
__global__ void k_final(float* __restrict__ out, const float* __restrict__ b) {
    int t = blockIdx.x * blockDim.x + threadIdx.x;   // one float4 per thread
    if (t < NN * (D / 4)) {
        int c = (t & 15) << 2;
        float4 v = *(float4*)&out[t * 4];
        v.x = fmaxf(v.x + __ldg(&b[c + 0]), 0.f);
        v.y = fmaxf(v.y + __ldg(&b[c + 1]), 0.f);
        v.z = fmaxf(v.z + __ldg(&b[c + 2]), 0.f);
        v.w = fmaxf(v.w + __ldg(&b[c + 3]), 0.f);
        *(float4*)&out[t * 4] = v;
    }
}

// ---------------------------------------------------------------------------
extern "C" void kernel_launch(void* const* d_in, const int* in_sizes, int n_in,
                              void* d_out, int out_size) {
    const float* x  = (const float*)d_in[0];
    const int*   ei = (const int*)d_in[1];     // [2, NE] row-major
    const float* ea = (const float*)d_in[2];
    const float* W  = (const float*)d_in[3];
    const float* b  = (const float*)d_in[4];
    float* out = (float*)d_out;

    const int* src = ei;
    const int* dst = ei + NE;

    k_init_deg<<<(NN + 255) / 256, 256>>>();
    k_deg<<<(NE + 255) / 256, 256>>>(dst, ea);
    k_rsqrt<<<(NN + 255) / 256, 256>>>();
    k_gemm<<<(NN + 8 * ROWS_PER_WARP - 1) / (8 * ROWS_PER_WARP), 256>>>(x, W, out);
    {
        long long threads = (long long)NE * 16;
        int blocks = (int)((threads + 255) / 256);
        k_msg<<<blocks, 256>>>(src, dst, ea, out);
    }
    k_final<<<(NN * (D / 4) + 255) / 256, 256>>>(out, b);
}

// round 2
// speedup vs baseline: 1.2779x; 1.2779x over previous
#include <cuda_runtime.h>

#define NN 100000
#define NE 1200000
#define D  64

// Scratch (device globals — no allocation allowed)
__device__ float g_dis[NN];        // degree, then rsqrt(degree)
__device__ float g_h[NN * D];      // h = x @ W^T

// ---------------------------------------------------------------------------
// 1) deg init (self-loop contributes weight 1.0)
__global__ void k_init_deg() {
    int i = blockIdx.x * blockDim.x + threadIdx.x;
    if (i < NN) g_dis[i] = 1.0f;
}

// 2) deg scatter: deg[dst] += ew
__global__ void k_deg(const int* __restrict__ dst, const float* __restrict__ ew) {
    int e = blockIdx.x * blockDim.x + threadIdx.x;
    if (e < NE) atomicAdd(&g_dis[dst[e]], ew[e]);
}

// 3) dis = rsqrt(deg)   (deg >= 1 always, matches where(deg>0, rsqrt, 0))
__global__ void k_rsqrt() {
    int i = blockIdx.x * blockDim.x + threadIdx.x;
    if (i < NN) g_dis[i] = rsqrtf(g_dis[i]);
}

// ---------------------------------------------------------------------------
// 4) GEMM h = x @ W^T, fused with self-loop contribution:
//    g_h[i] = h_i ;  out[i] = dis[i]^2 * h_i
// Register-blocked smem GEMM: 256 threads, 128 rows/block, each thread
// computes a 4-row x 8-col micro-tile (32 FMAs per 6 LDS per k-step).
#define GROWS 128
__global__ __launch_bounds__(256) void k_gemm(const float* __restrict__ x,
                                              const float* __restrict__ W,
                                              float* __restrict__ out) {
    __shared__ float Wt[D * D];          // Wt[k*64 + j] = W[j][k]
    __shared__ float Xs[GROWS * 65];     // padded: 65 words/row

    // Load W transposed (coalesced read)
    for (int t = threadIdx.x; t < D * D; t += 256) {
        int j = t >> 6, k = t & 63;
        Wt[k * D + j] = W[t];
    }

    const int base = blockIdx.x * GROWS;

    // Load X tile, float4-coalesced: 128 rows x 16 float4
    for (int t = threadIdx.x; t < GROWS * 16; t += 256) {
        int r = t >> 4, c4 = (t & 15) << 2;
        int gi = base + r;
        float4 v = make_float4(0.f, 0.f, 0.f, 0.f);
        if (gi < NN) v = *(const float4*)&x[gi * D + c4];
        Xs[r * 65 + c4 + 0] = v.x;
        Xs[r * 65 + c4 + 1] = v.y;
        Xs[r * 65 + c4 + 2] = v.z;
        Xs[r * 65 + c4 + 3] = v.w;
    }
    __syncthreads();

    const int cg = threadIdx.x & 7;      // col group: cols [8*cg, 8*cg+8)
    const int rg = threadIdx.x >> 3;     // row group: rows rg*4 .. rg*4+3
    const int col = cg << 3;

    float acc[4][8];
    #pragma unroll
    for (int r = 0; r < 4; r++)
        #pragma unroll
        for (int j = 0; j < 8; j++) acc[r][j] = 0.f;

    #pragma unroll 4
    for (int k = 0; k < D; k++) {
        float4 w0 = *(const float4*)&Wt[k * D + col];
        float4 w1 = *(const float4*)&Wt[k * D + col + 4];
        float wv[8] = {w0.x, w0.y, w0.z, w0.w, w1.x, w1.y, w1.z, w1.w};
        #pragma unroll
        for (int r = 0; r < 4; r++) {
            float xv = Xs[(rg * 4 + r) * 65 + k];
            #pragma unroll
            for (int j = 0; j < 8; j++)
                acc[r][j] = fmaf(xv, wv[j], acc[r][j]);
        }
    }

    // Epilogue: write g_h and out (out = dis^2 * h)
    #pragma unroll
    for (int r = 0; r < 4; r++) {
        int gi = base + rg * 4 + r;
        if (gi >= NN) continue;
        float s  = g_dis[gi];
        float ss = s * s;
        float4 h0 = make_float4(acc[r][0], acc[r][1], acc[r][2], acc[r][3]);
        float4 h1 = make_float4(acc[r][4], acc[r][5], acc[r][6], acc[r][7]);
        *(float4*)&g_h[gi * D + col]     = h0;
        *(float4*)&g_h[gi * D + col + 4] = h1;
        float4 o0 = make_float4(ss * h0.x, ss * h0.y, ss * h0.z, ss * h0.w);
        float4 o1 = make_float4(ss * h1.x, ss * h1.y, ss * h1.z, ss * h1.w);
        *(float4*)&out[gi * D + col]     = o0;
        *(float4*)&out[gi * D + col + 4] = o1;
    }
}

// ---------------------------------------------------------------------------
// 5) Edge scatter: out[dst] += dis[src]*ew*dis[dst] * h[src]
// One thread handles a float4 chunk (16 threads per edge).
__global__ __launch_bounds__(256) void k_msg(const int* __restrict__ src,
                                             const int* __restrict__ dst,
                                             const float* __restrict__ ew,
                                             float* __restrict__ out) {
    long long t = (long long)blockIdx.x * blockDim.x + threadIdx.x;
    int e = (int)(t >> 4);
    if (e >= NE) return;
    int c = (int)(t & 15) << 2;

    int r  = src[e];
    int cl = dst[e];
    float norm = g_dis[r] * ew[e] * g_dis[cl];

    float4 hv = *(const float4*)&g_h[r * D + c];
    float4 m;
    m.x = norm * hv.x;
    m.y = norm * hv.y;
    m.z = norm * hv.z;
    m.w = norm * hv.w;

    float* p = &out[cl * D + c];
    asm volatile("red.global.add.v4.f32 [%0], {%1, %2, %3, %4};"
                 :: "l"(p), "f"(m.x), "f"(m.y), "f"(m.z), "f"(m.w)
                 : "memory");
}

// ---------------------------------------------------------------------------
// 6) out = relu(out + b)
__global__ void k_final(float* __restrict__ out, const float* __restrict__ b) {
    int t = blockIdx.x * blockDim.x + threadIdx.x;   // one float4 per thread
    if (t < NN * (D / 4)) {
        int c = (t & 15) << 2;
        float4 v = *(float4*)&out[t * 4];
        v.x = fmaxf(v.x + __ldg(&b[c + 0]), 0.f);
        v.y = fmaxf(v.y + __ldg(&b[c + 1]), 0.f);
        v.z = fmaxf(v.z + __ldg(&b[c + 2]), 0.f);
        v.w = fmaxf(v.w + __ldg(&b[c + 3]), 0.f);
        *(float4*)&out[t * 4] = v;
    }
}

// ---------------------------------------------------------------------------
extern "C" void kernel_launch(void* const* d_in, const int* in_sizes, int n_in,
                              void* d_out, int out_size) {
    const float* x  = (const float*)d_in[0];
    const int*   ei = (const int*)d_in[1];     // [2, NE] row-major
    const float* ea = (const float*)d_in[2];
    const float* W  = (const float*)d_in[3];
    const float* b  = (const float*)d_in[4];
    float* out = (float*)d_out;

    const int* src = ei;
    const int* dst = ei + NE;

    k_init_deg<<<(NN + 255) / 256, 256>>>();
    k_deg<<<(NE + 255) / 256, 256>>>(dst, ea);
    k_rsqrt<<<(NN + 255) / 256, 256>>>();
    k_gemm<<<(NN + GROWS - 1) / GROWS, 256>>>(x, W, out);
    {
        long long threads = (long long)NE * 16;
        int blocks = (int)((threads + 255) / 256);
        k_msg<<<blocks, 256>>>(src, dst, ea, out);
    }
    k_final<<<(NN * (D / 4) + 255) / 256, 256>>>(out, b);
}